// round 9
// baseline (speedup 1.0000x reference)
#include <cuda_runtime.h>
#include <math.h>

// Problem constants
//   x:     (1, 128, 32, 32, 32) fp32
//   w_qkv: (384, 128) fp32
//   subsample ::2 -> (128, 16,16,16), N = 4096 tokens
//   HEADS=4, head_dim=32, d_half=16, scale=1/sqrt(32), LAMBDA=0.1
//   out:   (1, 128, 16,16,16) fp32 ; flat index = h*131072 + n*32 + d

#define N_TOK    4096
#define LAMBDA_F 0.1f
#define KT_STRIDE 36
#define P_STRIDE  72

// Scratch (device globals — no allocation)
__device__ float g_qkv[384 * 4096];        // q,k rows: [o][n], o = h*96 + r (r<64 used)
__device__ float g_vT[4 * 4096 * 32];      // v transposed: [h][n][d]

// ---------------------------------------------------------------------------
// Kernel 1: QKV projection with strided (::2) gather. (unchanged from R4)
// ---------------------------------------------------------------------------
__global__ __launch_bounds__(256) void qkv_proj_kernel(const float* __restrict__ x,
                                                       const float* __restrict__ w) {
    __shared__ float sW[64 * 64];   // [o_local][k_local]
    __shared__ float sX[64 * 64];   // [c_local][n_local]
    const int tid = threadIdx.x;
    const int n0 = blockIdx.x * 64;
    const int o0 = blockIdx.y * 64;
    const int tx = tid & 15;        // n group (4 cols)
    const int ty = tid >> 4;        // o group (4 rows)

    float acc[4][4] = {};

    for (int k0 = 0; k0 < 128; k0 += 64) {
        __syncthreads();
        for (int i = tid; i < 64 * 16; i += 256) {
            int r = i >> 4, q4 = i & 15;
            *(float4*)&sW[r * 64 + q4 * 4] =
                *(const float4*)&w[(o0 + r) * 128 + k0 + q4 * 4];
        }
        for (int i = tid; i < 64 * 64; i += 256) {
            int cl = i >> 6, j = i & 63;
            int n = n0 + j;
            int hh = n >> 8, ww = (n >> 4) & 15, zz = n & 15;
            sX[cl * 64 + j] = x[(k0 + cl) * 32768 + hh * 2048 + ww * 64 + zz * 2];
        }
        __syncthreads();

        #pragma unroll
        for (int k = 0; k < 64; k += 4) {
            float xk[4][4];
            #pragma unroll
            for (int kk = 0; kk < 4; kk++) {
                float4 xv = *(float4*)&sX[(k + kk) * 64 + 4 * tx];
                xk[kk][0] = xv.x; xk[kk][1] = xv.y; xk[kk][2] = xv.z; xk[kk][3] = xv.w;
            }
            #pragma unroll
            for (int i = 0; i < 4; i++) {
                float4 wv = *(float4*)&sW[(4 * ty + i) * 64 + k];
                float wk[4] = {wv.x, wv.y, wv.z, wv.w};
                #pragma unroll
                for (int kk = 0; kk < 4; kk++)
                    #pragma unroll
                    for (int j = 0; j < 4; j++)
                        acc[i][j] += wk[kk] * xk[kk][j];
            }
        }
    }

    #pragma unroll
    for (int i = 0; i < 4; i++) {
        int o = o0 + 4 * ty + i;
        int r = o % 96;
        if (r < 64) {
            *(float4*)&g_qkv[o * 4096 + n0 + 4 * tx] =
                make_float4(acc[i][0], acc[i][1], acc[i][2], acc[i][3]);
        } else {
            int h = o / 96, d = r - 64;
            int nb = n0 + 4 * tx;
            #pragma unroll
            for (int j = 0; j < 4; j++)
                g_vT[(h * 4096 + nb + j) * 32 + d] = acc[i][j];
        }
    }
}

// ---------------------------------------------------------------------------
// Kernel 2: dual-softmax attention, no-max-shift (scores bounded ~|5|).
// grid (128 row-tiles, 4 heads) = 512 CTAs, 256 threads.
// M=32 query rows per CTA, Kc=64 keys per tile, 8 threads per row.
// Q lives in 32 registers per thread (constant across tiles).
// Thread (row, seg): scores for cols {jj*8+seg}, PV for out dims seg*4..+3.
// ---------------------------------------------------------------------------
__global__ __launch_bounds__(256) void diff_attn_kernel(float* __restrict__ out) {
    __shared__ float sKT[64 * KT_STRIDE];  // [key][d], pad 36 -> conflict-free
    __shared__ float sV [64 * 32];         // [key][d]
    __shared__ float sP1[32 * P_STRIDE];   // probs half-1, pad 72
    __shared__ float sP2[32 * P_STRIDE];   // probs half-2

    const int tid = threadIdx.x;
    const int h   = blockIdx.y;
    const int i0  = blockIdx.x * 32;
    const int row = tid >> 3;    // 0..31
    const int seg = tid & 7;     // 0..7
    const float scale = 0.17677669529663687f;   // 1/sqrt(32)

    const float* qb = g_qkv + (h * 96) * 4096;
    const float* kb = qb + 32 * 4096;
    const float* vb = g_vT + h * 4096 * 32;

    // Q row in registers (scale folded in) — constant for all key tiles
    float q[32];
    #pragma unroll
    for (int d = 0; d < 32; d++)
        q[d] = qb[d * 4096 + i0 + row] * scale;

    float o1[4] = {}, o2[4] = {};
    float l1 = 0.f, l2 = 0.f;

    for (int j0 = 0; j0 < N_TOK; j0 += 64) {
        __syncthreads();   // all warps done reading previous sKT/sV
        // fill K tile transposed: global coalesced (d-major rows of 64)
        for (int i = tid; i < 2048; i += 256) {
            int d = i >> 6, j = i & 63;
            sKT[j * KT_STRIDE + d] = kb[d * 4096 + j0 + j];
        }
        // fill V tile: linear copy, coalesced + conflict-free
        for (int i = tid; i < 2048; i += 256)
            sV[i] = vb[j0 * 32 + i];
        __syncthreads();

        // ---- scores + exp (both halves); Q in regs, K vectorized ----
        #pragma unroll
        for (int jj = 0; jj < 8; jj++) {
            const int col = jj * 8 + seg;                 // interleaved ownership
            const float* kp = &sKT[col * KT_STRIDE];
            float s1 = 0.f, s2 = 0.f;
            #pragma unroll
            for (int i = 0; i < 4; i++) {
                float4 kf = *(const float4*)&kp[4 * i];
                s1 += q[4*i+0] * kf.x + q[4*i+1] * kf.y
                    + q[4*i+2] * kf.z + q[4*i+3] * kf.w;
            }
            #pragma unroll
            for (int i = 4; i < 8; i++) {
                float4 kf = *(const float4*)&kp[4 * i];
                s2 += q[4*i+0] * kf.x + q[4*i+1] * kf.y
                    + q[4*i+2] * kf.z + q[4*i+3] * kf.w;
            }
            float e1 = __expf(s1);
            float e2 = __expf(s2);
            l1 += e1; l2 += e2;
            sP1[row * P_STRIDE + col] = e1;
            sP2[row * P_STRIDE + col] = e2;
        }
        __syncwarp();   // probs consumed only by the same warp's row lanes

        // ---- P @ V (both states share V) ----
        const float* p1r = &sP1[row * P_STRIDE];
        const float* p2r = &sP2[row * P_STRIDE];
        const float* vpb = &sV[seg * 4];
        #pragma unroll 4
        for (int jj = 0; jj < 16; jj++) {
            float4 p1 = *(const float4*)&p1r[jj * 4];
            float4 p2 = *(const float4*)&p2r[jj * 4];
            const float* vp = vpb + jj * 4 * 32;
            float4 v0 = *(const float4*)&vp[0];
            float4 v1 = *(const float4*)&vp[32];
            float4 v2 = *(const float4*)&vp[64];
            float4 v3 = *(const float4*)&vp[96];
            o1[0] += p1.x*v0.x + p1.y*v1.x + p1.z*v2.x + p1.w*v3.x;
            o1[1] += p1.x*v0.y + p1.y*v1.y + p1.z*v2.y + p1.w*v3.y;
            o1[2] += p1.x*v0.z + p1.y*v1.z + p1.z*v2.z + p1.w*v3.z;
            o1[3] += p1.x*v0.w + p1.y*v1.w + p1.z*v2.w + p1.w*v3.w;
            o2[0] += p2.x*v0.x + p2.y*v1.x + p2.z*v2.x + p2.w*v3.x;
            o2[1] += p2.x*v0.y + p2.y*v1.y + p2.z*v2.y + p2.w*v3.y;
            o2[2] += p2.x*v0.z + p2.y*v1.z + p2.z*v2.z + p2.w*v3.z;
            o2[3] += p2.x*v0.w + p2.y*v1.w + p2.z*v2.w + p2.w*v3.w;
        }
    }

    // epilogue: reduce l across the 8 lanes of this row, then combine
    #pragma unroll
    for (int s = 1; s < 8; s <<= 1) {
        l1 += __shfl_xor_sync(0xffffffffu, l1, s);
        l2 += __shfl_xor_sync(0xffffffffu, l2, s);
    }
    float inv1 = 1.f / l1;
    float inv2 = LAMBDA_F / l2;
    float4 r;
    r.x = o1[0] * inv1 - o2[0] * inv2;
    r.y = o1[1] * inv1 - o2[1] * inv2;
    r.z = o1[2] * inv1 - o2[2] * inv2;
    r.w = o1[3] * inv1 - o2[3] * inv2;
    *(float4*)&out[h * (N_TOK * 32) + (i0 + row) * 32 + seg * 4] = r;
}

// ---------------------------------------------------------------------------
extern "C" void kernel_launch(void* const* d_in, const int* in_sizes, int n_in,
                              void* d_out, int out_size) {
    const float* x = (const float*)d_in[0];       // (1,128,32,32,32)
    const float* w = (const float*)d_in[1];       // (384,128)
    float* out = (float*)d_out;                   // (1,128,16,16,16) fp32

    qkv_proj_kernel<<<dim3(64, 6), 256>>>(x, w);
    diff_attn_kernel<<<dim3(128, 4), 256>>>(out);
}

// round 10
// speedup vs baseline: 1.0012x; 1.0012x over previous
#include <cuda_runtime.h>
#include <math.h>

// Problem constants
//   x:     (1, 128, 32, 32, 32) fp32
//   w_qkv: (384, 128) fp32
//   subsample ::2 -> (128, 16,16,16), N = 4096 tokens
//   HEADS=4, head_dim=32, d_half=16, scale=1/sqrt(32), LAMBDA=0.1
//   out:   (1, 128, 16,16,16) fp32 ; flat index = h*131072 + n*32 + d

#define N_TOK    4096
#define LAMBDA_F 0.1f
#define KT_STRIDE 36
#define P_STRIDE  72

// Scratch (device globals — no allocation)
__device__ float g_qkv[384 * 4096];        // q,k rows: [o][n], o = h*96 + r (r<64 used)
__device__ float g_vT[4 * 4096 * 32];      // v transposed: [h][n][d]

// ---------------------------------------------------------------------------
// Kernel 1: QKV projection with strided (::2) gather. (unchanged from R4)
// ---------------------------------------------------------------------------
__global__ __launch_bounds__(256) void qkv_proj_kernel(const float* __restrict__ x,
                                                       const float* __restrict__ w) {
    __shared__ float sW[64 * 64];   // [o_local][k_local]
    __shared__ float sX[64 * 64];   // [c_local][n_local]
    const int tid = threadIdx.x;
    const int n0 = blockIdx.x * 64;
    const int o0 = blockIdx.y * 64;
    const int tx = tid & 15;        // n group (4 cols)
    const int ty = tid >> 4;        // o group (4 rows)

    float acc[4][4] = {};

    for (int k0 = 0; k0 < 128; k0 += 64) {
        __syncthreads();
        for (int i = tid; i < 64 * 16; i += 256) {
            int r = i >> 4, q4 = i & 15;
            *(float4*)&sW[r * 64 + q4 * 4] =
                *(const float4*)&w[(o0 + r) * 128 + k0 + q4 * 4];
        }
        for (int i = tid; i < 64 * 64; i += 256) {
            int cl = i >> 6, j = i & 63;
            int n = n0 + j;
            int hh = n >> 8, ww = (n >> 4) & 15, zz = n & 15;
            sX[cl * 64 + j] = x[(k0 + cl) * 32768 + hh * 2048 + ww * 64 + zz * 2];
        }
        __syncthreads();

        #pragma unroll
        for (int k = 0; k < 64; k += 4) {
            float xk[4][4];
            #pragma unroll
            for (int kk = 0; kk < 4; kk++) {
                float4 xv = *(float4*)&sX[(k + kk) * 64 + 4 * tx];
                xk[kk][0] = xv.x; xk[kk][1] = xv.y; xk[kk][2] = xv.z; xk[kk][3] = xv.w;
            }
            #pragma unroll
            for (int i = 0; i < 4; i++) {
                float4 wv = *(float4*)&sW[(4 * ty + i) * 64 + k];
                float wk[4] = {wv.x, wv.y, wv.z, wv.w};
                #pragma unroll
                for (int kk = 0; kk < 4; kk++)
                    #pragma unroll
                    for (int j = 0; j < 4; j++)
                        acc[i][j] += wk[kk] * xk[kk][j];
            }
        }
    }

    #pragma unroll
    for (int i = 0; i < 4; i++) {
        int o = o0 + 4 * ty + i;
        int r = o % 96;
        if (r < 64) {
            *(float4*)&g_qkv[o * 4096 + n0 + 4 * tx] =
                make_float4(acc[i][0], acc[i][1], acc[i][2], acc[i][3]);
        } else {
            int h = o / 96, d = r - 64;
            int nb = n0 + 4 * tx;
            #pragma unroll
            for (int j = 0; j < 4; j++)
                g_vT[(h * 4096 + nb + j) * 32 + d] = acc[i][j];
        }
    }
}

// ---------------------------------------------------------------------------
// Kernel 2: dual-softmax attention, no-max-shift (scores bounded ~|5|).
// grid (128 row-tiles, 4 heads) = 512 CTAs, 256 threads.
// M=32 query rows per CTA, Kc=64 keys per tile, 8 threads per row.
// Q lives in 32 registers per thread (constant across tiles).
// Thread (row, seg): scores for cols {jj*8+seg}, PV for out dims seg*4..+3.
// ---------------------------------------------------------------------------
__global__ __launch_bounds__(256) void diff_attn_kernel(float* __restrict__ out) {
    __shared__ float sKT[64 * KT_STRIDE];  // [key][d], pad 36 -> conflict-free
    __shared__ float sV [64 * 32];         // [key][d]
    __shared__ float sP1[32 * P_STRIDE];   // probs half-1, pad 72
    __shared__ float sP2[32 * P_STRIDE];   // probs half-2

    const int tid = threadIdx.x;
    const int h   = blockIdx.y;
    const int i0  = blockIdx.x * 32;
    const int row = tid >> 3;    // 0..31
    const int seg = tid & 7;     // 0..7
    const float scale = 0.17677669529663687f;   // 1/sqrt(32)

    const float* qb = g_qkv + (h * 96) * 4096;
    const float* kb = qb + 32 * 4096;
    const float* vb = g_vT + h * 4096 * 32;

    // Q row in registers (scale folded in) — constant for all key tiles
    float q[32];
    #pragma unroll
    for (int d = 0; d < 32; d++)
        q[d] = qb[d * 4096 + i0 + row] * scale;

    float o1[4] = {}, o2[4] = {};
    float l1 = 0.f, l2 = 0.f;

    for (int j0 = 0; j0 < N_TOK; j0 += 64) {
        __syncthreads();   // all warps done reading previous sKT/sV
        // fill K tile transposed: global coalesced (d-major rows of 64)
        for (int i = tid; i < 2048; i += 256) {
            int d = i >> 6, j = i & 63;
            sKT[j * KT_STRIDE + d] = kb[d * 4096 + j0 + j];
        }
        // fill V tile: linear copy, coalesced + conflict-free
        for (int i = tid; i < 2048; i += 256)
            sV[i] = vb[j0 * 32 + i];
        __syncthreads();

        // ---- scores + exp (both halves); Q in regs, K vectorized ----
        #pragma unroll
        for (int jj = 0; jj < 8; jj++) {
            const int col = jj * 8 + seg;                 // interleaved ownership
            const float* kp = &sKT[col * KT_STRIDE];
            float s1 = 0.f, s2 = 0.f;
            #pragma unroll
            for (int i = 0; i < 4; i++) {
                float4 kf = *(const float4*)&kp[4 * i];
                s1 += q[4*i+0] * kf.x + q[4*i+1] * kf.y
                    + q[4*i+2] * kf.z + q[4*i+3] * kf.w;
            }
            #pragma unroll
            for (int i = 4; i < 8; i++) {
                float4 kf = *(const float4*)&kp[4 * i];
                s2 += q[4*i+0] * kf.x + q[4*i+1] * kf.y
                    + q[4*i+2] * kf.z + q[4*i+3] * kf.w;
            }
            float e1 = __expf(s1);
            float e2 = __expf(s2);
            l1 += e1; l2 += e2;
            sP1[row * P_STRIDE + col] = e1;
            sP2[row * P_STRIDE + col] = e2;
        }
        __syncwarp();   // probs consumed only by the same warp's row lanes

        // ---- P @ V (both states share V) ----
        const float* p1r = &sP1[row * P_STRIDE];
        const float* p2r = &sP2[row * P_STRIDE];
        const float* vpb = &sV[seg * 4];
        #pragma unroll 4
        for (int jj = 0; jj < 16; jj++) {
            float4 p1 = *(const float4*)&p1r[jj * 4];
            float4 p2 = *(const float4*)&p2r[jj * 4];
            const float* vp = vpb + jj * 4 * 32;
            float4 v0 = *(const float4*)&vp[0];
            float4 v1 = *(const float4*)&vp[32];
            float4 v2 = *(const float4*)&vp[64];
            float4 v3 = *(const float4*)&vp[96];
            o1[0] += p1.x*v0.x + p1.y*v1.x + p1.z*v2.x + p1.w*v3.x;
            o1[1] += p1.x*v0.y + p1.y*v1.y + p1.z*v2.y + p1.w*v3.y;
            o1[2] += p1.x*v0.z + p1.y*v1.z + p1.z*v2.z + p1.w*v3.z;
            o1[3] += p1.x*v0.w + p1.y*v1.w + p1.z*v2.w + p1.w*v3.w;
            o2[0] += p2.x*v0.x + p2.y*v1.x + p2.z*v2.x + p2.w*v3.x;
            o2[1] += p2.x*v0.y + p2.y*v1.y + p2.z*v2.y + p2.w*v3.y;
            o2[2] += p2.x*v0.z + p2.y*v1.z + p2.z*v2.z + p2.w*v3.z;
            o2[3] += p2.x*v0.w + p2.y*v1.w + p2.z*v2.w + p2.w*v3.w;
        }
    }

    // epilogue: reduce l across the 8 lanes of this row, then combine
    #pragma unroll
    for (int s = 1; s < 8; s <<= 1) {
        l1 += __shfl_xor_sync(0xffffffffu, l1, s);
        l2 += __shfl_xor_sync(0xffffffffu, l2, s);
    }
    float inv1 = 1.f / l1;
    float inv2 = LAMBDA_F / l2;
    float4 r;
    r.x = o1[0] * inv1 - o2[0] * inv2;
    r.y = o1[1] * inv1 - o2[1] * inv2;
    r.z = o1[2] * inv1 - o2[2] * inv2;
    r.w = o1[3] * inv1 - o2[3] * inv2;
    *(float4*)&out[h * (N_TOK * 32) + (i0 + row) * 32 + seg * 4] = r;
}

// ---------------------------------------------------------------------------
extern "C" void kernel_launch(void* const* d_in, const int* in_sizes, int n_in,
                              void* d_out, int out_size) {
    const float* x = (const float*)d_in[0];       // (1,128,32,32,32)
    const float* w = (const float*)d_in[1];       // (384,128)
    float* out = (float*)d_out;                   // (1,128,16,16,16) fp32

    qkv_proj_kernel<<<dim3(64, 6), 256>>>(x, w);
    diff_attn_kernel<<<dim3(128, 4), 256>>>(out);
}

// round 12
// speedup vs baseline: 4.4973x; 4.4918x over previous
#include <cuda_runtime.h>
#include <cstdint>
#include <math.h>

// Problem constants
//   x: (1,128,32,32,32) fp32 ; w_qkv: (384,128) fp32
//   subsample ::2 -> N = 4096 tokens, HEADS=4, head_dim=32, d_half=16
//   scale=1/sqrt(32), LAMBDA=0.1
//   out flat index = h*131072 + n*32 + d  (validated R4/R5)

#define N_TOK    4096
#define LAMBDA_F 0.1f

// Scratch (device globals — no allocation)
__device__ float g_qkv[384 * 4096];        // q,k rows: [o][n], o = h*96 + r
__device__ float g_vT[4 * 4096 * 32];      // v: [h][n][d]

// ---------------------------------------------------------------------------
__device__ __forceinline__ uint32_t f2tf32(float x) {
    uint32_t t;
    asm("cvt.rna.tf32.f32 %0, %1;" : "=r"(t) : "f"(x));
    return t;
}
// D += A * B  (m16n8k8, tf32 in, fp32 accum) — plain warp-level MMA (sm_80+)
__device__ __forceinline__ void mma_tf32(float* d, const uint32_t* a, const uint32_t* b) {
    asm volatile(
        "mma.sync.aligned.m16n8k8.row.col.f32.tf32.tf32.f32 "
        "{%0,%1,%2,%3}, {%4,%5,%6,%7}, {%8,%9}, {%0,%1,%2,%3};"
        : "+f"(d[0]), "+f"(d[1]), "+f"(d[2]), "+f"(d[3])
        : "r"(a[0]), "r"(a[1]), "r"(a[2]), "r"(a[3]), "r"(b[0]), "r"(b[1]));
}

// ===========================================================================
// Kernel 1: QKV projection with strided (::2) gather. (unchanged, proven)
// ===========================================================================
__global__ __launch_bounds__(256) void qkv_proj_kernel(const float* __restrict__ x,
                                                       const float* __restrict__ w) {
    __shared__ float sW[64 * 64];
    __shared__ float sX[64 * 64];
    const int tid = threadIdx.x;
    const int n0 = blockIdx.x * 64;
    const int o0 = blockIdx.y * 64;
    const int tx = tid & 15;
    const int ty = tid >> 4;

    float acc[4][4] = {};

    for (int k0 = 0; k0 < 128; k0 += 64) {
        __syncthreads();
        for (int i = tid; i < 64 * 16; i += 256) {
            int r = i >> 4, q4 = i & 15;
            *(float4*)&sW[r * 64 + q4 * 4] =
                *(const float4*)&w[(o0 + r) * 128 + k0 + q4 * 4];
        }
        for (int i = tid; i < 64 * 64; i += 256) {
            int cl = i >> 6, j = i & 63;
            int n = n0 + j;
            int hh = n >> 8, ww = (n >> 4) & 15, zz = n & 15;
            sX[cl * 64 + j] = x[(k0 + cl) * 32768 + hh * 2048 + ww * 64 + zz * 2];
        }
        __syncthreads();

        #pragma unroll
        for (int k = 0; k < 64; k += 4) {
            float xk[4][4];
            #pragma unroll
            for (int kk = 0; kk < 4; kk++) {
                float4 xv = *(float4*)&sX[(k + kk) * 64 + 4 * tx];
                xk[kk][0] = xv.x; xk[kk][1] = xv.y; xk[kk][2] = xv.z; xk[kk][3] = xv.w;
            }
            #pragma unroll
            for (int i = 0; i < 4; i++) {
                float4 wv = *(float4*)&sW[(4 * ty + i) * 64 + k];
                float wk[4] = {wv.x, wv.y, wv.z, wv.w};
                #pragma unroll
                for (int kk = 0; kk < 4; kk++)
                    #pragma unroll
                    for (int j = 0; j < 4; j++)
                        acc[i][j] += wk[kk] * xk[kk][j];
            }
        }
    }

    #pragma unroll
    for (int i = 0; i < 4; i++) {
        int o = o0 + 4 * ty + i;
        int r = o % 96;
        if (r < 64) {
            *(float4*)&g_qkv[o * 4096 + n0 + 4 * tx] =
                make_float4(acc[i][0], acc[i][1], acc[i][2], acc[i][3]);
        } else {
            int h = o / 96, d = r - 64;
            int nb = n0 + 4 * tx;
            #pragma unroll
            for (int j = 0; j < 4; j++)
                g_vT[(h * 4096 + nb + j) * 32 + d] = acc[i][j];
        }
    }
}

// ===========================================================================
// Kernel 2: dual-softmax attention via mma.sync tf32.
// grid (64 row-tiles, 4 heads) = 256 CTAs, 128 threads (4 warps x 16 rows).
// 32-key tiles; K/V double-buffered through registers (LDG prefetch).
// O accumulated in register fragments across all tiles (no online rescale).
// ===========================================================================
__global__ __launch_bounds__(128, 4) void diff_attn_mma(float* __restrict__ out) {
    __shared__ __align__(16) uint32_t sK[32 * 40];          // [dim][key], pad 40
    __shared__ __align__(16) uint32_t sV[32 * 40];          // [key][dim], pad 40
    __shared__ __align__(16) uint32_t sP[4 * 2 * 16 * 36];  // [warp][state][row][col36]

    const int tid  = threadIdx.x;
    const int lane = tid & 31;
    const int warp = tid >> 5;
    const int h    = blockIdx.y;
    const int i0   = blockIdx.x * 64;
    const float scale = 0.17677669529663687f;   // 1/sqrt(32)

    const float* qb = g_qkv + (h * 96) * 4096;
    const float* kb = qb + 32 * 4096;
    const float* vb = g_vT + h * 4096 * 32;

    const int qr = lane >> 2;   // 0..7
    const int qc = lane & 3;    // 0..3

    // ---- persistent Q fragments (rna->tf32, scale folded): [state][kc][4] ----
    uint32_t qf[2][2][4];
    {
        const int r = i0 + warp * 16 + qr;
        #pragma unroll
        for (int hf = 0; hf < 2; hf++)
            #pragma unroll
            for (int kc = 0; kc < 2; kc++) {
                int d = hf * 16 + kc * 8 + qc;
                qf[hf][kc][0] = f2tf32(qb[d * 4096 + r] * scale);
                qf[hf][kc][1] = f2tf32(qb[d * 4096 + r + 8] * scale);
                qf[hf][kc][2] = f2tf32(qb[(d + 4) * 4096 + r] * scale);
                qf[hf][kc][3] = f2tf32(qb[(d + 4) * 4096 + r + 8] * scale);
            }
    }

    float of[2][4][4] = {};    // [state][nc(dim 8-chunk)][frag]
    float lacc[2][2] = {};     // [state][lo/hi row]

    uint32_t* myP = sP + warp * (2 * 16 * 36);

    // prefetch mapping: 128 threads cover 32 rows x 8 float4-chunks, twice
    const int pd = tid >> 3;          // 0..15 (row id; +16 for second chunk)
    const int pc = (tid & 7) * 4;     // element offset

    float4 kfA, kfB, vfA, vfB;
    kfA = *(const float4*)&kb[pd * 4096 + pc];
    kfB = *(const float4*)&kb[(pd + 16) * 4096 + pc];
    vfA = *(const float4*)&vb[pd * 32 + pc];
    vfB = *(const float4*)&vb[(pd + 16) * 32 + pc];

    for (int jt = 0; jt < 128; jt++) {
        __syncthreads();   // previous tile's smem fully consumed
        *(float4*)&sK[pd * 40 + pc]        = kfA;
        *(float4*)&sK[(pd + 16) * 40 + pc] = kfB;
        *(float4*)&sV[pd * 40 + pc]        = vfA;
        *(float4*)&sV[(pd + 16) * 40 + pc] = vfB;
        __syncthreads();

        if (jt < 127) {     // prefetch next tile (latency hidden by compute)
            const int j0 = (jt + 1) * 32;
            kfA = *(const float4*)&kb[pd * 4096 + j0 + pc];
            kfB = *(const float4*)&kb[(pd + 16) * 4096 + j0 + pc];
            vfA = *(const float4*)&vb[(j0 + pd) * 32 + pc];
            vfB = *(const float4*)&vb[(j0 + pd + 16) * 32 + pc];
        }

        // ---- MMA1 + exp + P store, both states ----
        #pragma unroll
        for (int hf = 0; hf < 2; hf++) {
            float sf[4][4] = {};
            #pragma unroll
            for (int kc = 0; kc < 2; kc++) {
                const int drow = hf * 16 + kc * 8 + qc;
                #pragma unroll
                for (int nc = 0; nc < 4; nc++) {
                    uint32_t b[2];
                    b[0] = sK[drow * 40 + nc * 8 + qr];
                    b[1] = sK[(drow + 4) * 40 + nc * 8 + qr];
                    mma_tf32(sf[nc], qf[hf][kc], b);
                }
            }
            float ll = 0.f, lh = 0.f;
            uint32_t* pr = myP + hf * 576;
            #pragma unroll
            for (int nc = 0; nc < 4; nc++) {
                uint32_t t0 = f2tf32(__expf(sf[nc][0]));
                uint32_t t1 = f2tf32(__expf(sf[nc][1]));
                uint32_t t2 = f2tf32(__expf(sf[nc][2]));
                uint32_t t3 = f2tf32(__expf(sf[nc][3]));
                ll += __uint_as_float(t0) + __uint_as_float(t1);
                lh += __uint_as_float(t2) + __uint_as_float(t3);
                const int col = nc * 8 + qc * 2;
                *(uint2*)&pr[qr * 36 + col]       = make_uint2(t0, t1);
                *(uint2*)&pr[(qr + 8) * 36 + col] = make_uint2(t2, t3);
            }
            lacc[hf][0] += ll;
            lacc[hf][1] += lh;
        }
        __syncwarp();   // P produced/consumed within this warp

        // ---- PV: O_s += P_s x V (shared V fragments) ----
        #pragma unroll
        for (int kc = 0; kc < 4; kc++) {
            uint32_t a1[4], a2[4];
            const int c = kc * 8 + qc;
            a1[0] = myP[qr * 36 + c];
            a1[1] = myP[(qr + 8) * 36 + c];
            a1[2] = myP[qr * 36 + c + 4];
            a1[3] = myP[(qr + 8) * 36 + c + 4];
            const uint32_t* p2 = myP + 576;
            a2[0] = p2[qr * 36 + c];
            a2[1] = p2[(qr + 8) * 36 + c];
            a2[2] = p2[qr * 36 + c + 4];
            a2[3] = p2[(qr + 8) * 36 + c + 4];
            #pragma unroll
            for (int nc = 0; nc < 4; nc++) {
                uint32_t b[2];
                b[0] = sV[(kc * 8 + qc) * 40 + nc * 8 + qr];
                b[1] = sV[(kc * 8 + qc + 4) * 40 + nc * 8 + qr];
                mma_tf32(of[0][nc], a1, b);
                mma_tf32(of[1][nc], a2, b);
            }
        }
    }

    // ---- epilogue: quad-reduce l, combine states, store ----
    #pragma unroll
    for (int s = 1; s < 4; s <<= 1) {
        #pragma unroll
        for (int hf = 0; hf < 2; hf++) {
            lacc[hf][0] += __shfl_xor_sync(0xffffffffu, lacc[hf][0], s);
            lacc[hf][1] += __shfl_xor_sync(0xffffffffu, lacc[hf][1], s);
        }
    }
    const float il1_lo = 1.0f / lacc[0][0];
    const float il1_hi = 1.0f / lacc[0][1];
    const float il2_lo = LAMBDA_F / lacc[1][0];
    const float il2_hi = LAMBDA_F / lacc[1][1];

    const int rbase = h * (N_TOK * 32) + (i0 + warp * 16 + qr) * 32;
    #pragma unroll
    for (int nc = 0; nc < 4; nc++) {
        const int col = nc * 8 + qc * 2;
        float2 vlo, vhi;
        vlo.x = of[0][nc][0] * il1_lo - of[1][nc][0] * il2_lo;
        vlo.y = of[0][nc][1] * il1_lo - of[1][nc][1] * il2_lo;
        vhi.x = of[0][nc][2] * il1_hi - of[1][nc][2] * il2_hi;
        vhi.y = of[0][nc][3] * il1_hi - of[1][nc][3] * il2_hi;
        *(float2*)&out[rbase + col]          = vlo;
        *(float2*)&out[rbase + 8 * 32 + col] = vhi;
    }
}

// ===========================================================================
extern "C" void kernel_launch(void* const* d_in, const int* in_sizes, int n_in,
                              void* d_out, int out_size) {
    const float* x = (const float*)d_in[0];       // (1,128,32,32,32)
    const float* w = (const float*)d_in[1];       // (384,128)
    float* out = (float*)d_out;                   // (1,128,16,16,16) fp32

    qkv_proj_kernel<<<dim3(64, 6), 256>>>(x, w);
    diff_attn_mma<<<dim3(64, 4), 256 / 2>>>(out);
}

// round 13
// speedup vs baseline: 4.9170x; 1.0933x over previous
#include <cuda_runtime.h>
#include <cstdint>
#include <math.h>

// Problem constants
//   x: (1,128,32,32,32) fp32 ; w_qkv: (384,128) fp32
//   subsample ::2 -> N = 4096 tokens, HEADS=4, head_dim=32, d_half=16
//   scale=1/sqrt(32), LAMBDA=0.1
//   out flat index = h*131072 + n*32 + d  (validated R4/R5)

#define N_TOK    4096
#define LAMBDA_F 0.1f
#define NSPLIT   2
#define KEYS_PER_SPLIT (N_TOK / NSPLIT)
#define TILES_PER_SPLIT (KEYS_PER_SPLIT / 32)

// Scratch (device globals — no allocation)
__device__ float g_qkv[384 * 4096];        // q,k rows: [o][n], o = h*96 + r
__device__ float g_vT[4 * 4096 * 32];      // v: [h][n][d]
// split-K partials: o [split][h][row][state][d], l [split][h][row][state]
__device__ float g_po[NSPLIT * 4 * 4096 * 2 * 32];
__device__ float g_pl[NSPLIT * 4 * 4096 * 2];

// ---------------------------------------------------------------------------
__device__ __forceinline__ uint32_t f2tf32(float x) {
    uint32_t t;
    asm("cvt.rna.tf32.f32 %0, %1;" : "=r"(t) : "f"(x));
    return t;
}
// D += A * B  (m16n8k8, tf32 in, fp32 accum) — warp-level MMA (sm_80+ PTX)
__device__ __forceinline__ void mma_tf32(float* d, const uint32_t* a, const uint32_t* b) {
    asm volatile(
        "mma.sync.aligned.m16n8k8.row.col.f32.tf32.tf32.f32 "
        "{%0,%1,%2,%3}, {%4,%5,%6,%7}, {%8,%9}, {%0,%1,%2,%3};"
        : "+f"(d[0]), "+f"(d[1]), "+f"(d[2]), "+f"(d[3])
        : "r"(a[0]), "r"(a[1]), "r"(a[2]), "r"(a[3]), "r"(b[0]), "r"(b[1]));
}

// ===========================================================================
// Kernel 1: QKV projection with strided (::2) gather. (unchanged, proven)
// ===========================================================================
__global__ __launch_bounds__(256) void qkv_proj_kernel(const float* __restrict__ x,
                                                       const float* __restrict__ w) {
    __shared__ float sW[64 * 64];
    __shared__ float sX[64 * 64];
    const int tid = threadIdx.x;
    const int n0 = blockIdx.x * 64;
    const int o0 = blockIdx.y * 64;
    const int tx = tid & 15;
    const int ty = tid >> 4;

    float acc[4][4] = {};

    for (int k0 = 0; k0 < 128; k0 += 64) {
        __syncthreads();
        for (int i = tid; i < 64 * 16; i += 256) {
            int r = i >> 4, q4 = i & 15;
            *(float4*)&sW[r * 64 + q4 * 4] =
                *(const float4*)&w[(o0 + r) * 128 + k0 + q4 * 4];
        }
        for (int i = tid; i < 64 * 64; i += 256) {
            int cl = i >> 6, j = i & 63;
            int n = n0 + j;
            int hh = n >> 8, ww = (n >> 4) & 15, zz = n & 15;
            sX[cl * 64 + j] = x[(k0 + cl) * 32768 + hh * 2048 + ww * 64 + zz * 2];
        }
        __syncthreads();

        #pragma unroll
        for (int k = 0; k < 64; k += 4) {
            float xk[4][4];
            #pragma unroll
            for (int kk = 0; kk < 4; kk++) {
                float4 xv = *(float4*)&sX[(k + kk) * 64 + 4 * tx];
                xk[kk][0] = xv.x; xk[kk][1] = xv.y; xk[kk][2] = xv.z; xk[kk][3] = xv.w;
            }
            #pragma unroll
            for (int i = 0; i < 4; i++) {
                float4 wv = *(float4*)&sW[(4 * ty + i) * 64 + k];
                float wk[4] = {wv.x, wv.y, wv.z, wv.w};
                #pragma unroll
                for (int kk = 0; kk < 4; kk++)
                    #pragma unroll
                    for (int j = 0; j < 4; j++)
                        acc[i][j] += wk[kk] * xk[kk][j];
            }
        }
    }

    #pragma unroll
    for (int i = 0; i < 4; i++) {
        int o = o0 + 4 * ty + i;
        int r = o % 96;
        if (r < 64) {
            *(float4*)&g_qkv[o * 4096 + n0 + 4 * tx] =
                make_float4(acc[i][0], acc[i][1], acc[i][2], acc[i][3]);
        } else {
            int h = o / 96, d = r - 64;
            int nb = n0 + 4 * tx;
            #pragma unroll
            for (int j = 0; j < 4; j++)
                g_vT[(h * 4096 + nb + j) * 32 + d] = acc[i][j];
        }
    }
}

// ===========================================================================
// Kernel 2: dual-softmax attention via mma.sync tf32, split-K over z.
// grid (64 row-tiles, 4 heads, 2 splits) = 512 CTAs, 128 threads (4 warps).
// Each CTA: 64 query rows x 2048 keys (64 tiles of 32), raw partials out.
// ===========================================================================
__global__ __launch_bounds__(128, 4) void diff_attn_mma(void) {
    __shared__ __align__(16) uint32_t sK[32 * 40];          // [dim][key], pad 40
    __shared__ __align__(16) uint32_t sV[32 * 40];          // [key][dim], pad 40
    __shared__ __align__(16) uint32_t sP[4 * 2 * 16 * 36];  // [warp][state][row][col36]

    const int tid  = threadIdx.x;
    const int lane = tid & 31;
    const int warp = tid >> 5;
    const int h    = blockIdx.y;
    const int i0   = blockIdx.x * 64;
    const int spl  = blockIdx.z;
    const int kbase = spl * KEYS_PER_SPLIT;
    const float scale = 0.17677669529663687f;   // 1/sqrt(32)

    const float* qb = g_qkv + (h * 96) * 4096;
    const float* kb = qb + 32 * 4096;
    const float* vb = g_vT + h * 4096 * 32;

    const int qr = lane >> 2;   // 0..7
    const int qc = lane & 3;    // 0..3

    // ---- persistent Q fragments (rna->tf32, scale folded): [state][kc][4] ----
    uint32_t qf[2][2][4];
    {
        const int r = i0 + warp * 16 + qr;
        #pragma unroll
        for (int hf = 0; hf < 2; hf++)
            #pragma unroll
            for (int kc = 0; kc < 2; kc++) {
                int d = hf * 16 + kc * 8 + qc;
                qf[hf][kc][0] = f2tf32(qb[d * 4096 + r] * scale);
                qf[hf][kc][1] = f2tf32(qb[d * 4096 + r + 8] * scale);
                qf[hf][kc][2] = f2tf32(qb[(d + 4) * 4096 + r] * scale);
                qf[hf][kc][3] = f2tf32(qb[(d + 4) * 4096 + r + 8] * scale);
            }
    }

    float of[2][4][4] = {};    // [state][nc(dim 8-chunk)][frag]
    float lacc[2][2] = {};     // [state][lo/hi row]

    uint32_t* myP = sP + warp * (2 * 16 * 36);

    // prefetch mapping: 128 threads cover 32 rows x 8 float4-chunks, twice
    const int pd = tid >> 3;          // 0..15 (row id; +16 for second chunk)
    const int pc = (tid & 7) * 4;     // element offset

    float4 kfA, kfB, vfA, vfB;
    kfA = *(const float4*)&kb[pd * 4096 + kbase + pc];
    kfB = *(const float4*)&kb[(pd + 16) * 4096 + kbase + pc];
    vfA = *(const float4*)&vb[(kbase + pd) * 32 + pc];
    vfB = *(const float4*)&vb[(kbase + pd + 16) * 32 + pc];

    for (int jt = 0; jt < TILES_PER_SPLIT; jt++) {
        __syncthreads();   // previous tile's smem fully consumed
        *(float4*)&sK[pd * 40 + pc]        = kfA;
        *(float4*)&sK[(pd + 16) * 40 + pc] = kfB;
        *(float4*)&sV[pd * 40 + pc]        = vfA;
        *(float4*)&sV[(pd + 16) * 40 + pc] = vfB;
        __syncthreads();

        if (jt < TILES_PER_SPLIT - 1) {   // prefetch next tile
            const int j0 = kbase + (jt + 1) * 32;
            kfA = *(const float4*)&kb[pd * 4096 + j0 + pc];
            kfB = *(const float4*)&kb[(pd + 16) * 4096 + j0 + pc];
            vfA = *(const float4*)&vb[(j0 + pd) * 32 + pc];
            vfB = *(const float4*)&vb[(j0 + pd + 16) * 32 + pc];
        }

        // ---- MMA1 + exp + P store, both states ----
        #pragma unroll
        for (int hf = 0; hf < 2; hf++) {
            float sf[4][4] = {};
            #pragma unroll
            for (int kc = 0; kc < 2; kc++) {
                const int drow = hf * 16 + kc * 8 + qc;
                #pragma unroll
                for (int nc = 0; nc < 4; nc++) {
                    uint32_t b[2];
                    b[0] = sK[drow * 40 + nc * 8 + qr];
                    b[1] = sK[(drow + 4) * 40 + nc * 8 + qr];
                    mma_tf32(sf[nc], qf[hf][kc], b);
                }
            }
            float ll = 0.f, lh = 0.f;
            uint32_t* pr = myP + hf * 576;
            #pragma unroll
            for (int nc = 0; nc < 4; nc++) {
                uint32_t t0 = f2tf32(__expf(sf[nc][0]));
                uint32_t t1 = f2tf32(__expf(sf[nc][1]));
                uint32_t t2 = f2tf32(__expf(sf[nc][2]));
                uint32_t t3 = f2tf32(__expf(sf[nc][3]));
                ll += __uint_as_float(t0) + __uint_as_float(t1);
                lh += __uint_as_float(t2) + __uint_as_float(t3);
                const int col = nc * 8 + qc * 2;
                *(uint2*)&pr[qr * 36 + col]       = make_uint2(t0, t1);
                *(uint2*)&pr[(qr + 8) * 36 + col] = make_uint2(t2, t3);
            }
            lacc[hf][0] += ll;
            lacc[hf][1] += lh;
        }
        __syncwarp();   // P produced/consumed within this warp

        // ---- PV: O_s += P_s x V (shared V fragments) ----
        #pragma unroll
        for (int kc = 0; kc < 4; kc++) {
            uint32_t a1[4], a2[4];
            const int c = kc * 8 + qc;
            a1[0] = myP[qr * 36 + c];
            a1[1] = myP[(qr + 8) * 36 + c];
            a1[2] = myP[qr * 36 + c + 4];
            a1[3] = myP[(qr + 8) * 36 + c + 4];
            const uint32_t* p2 = myP + 576;
            a2[0] = p2[qr * 36 + c];
            a2[1] = p2[(qr + 8) * 36 + c];
            a2[2] = p2[qr * 36 + c + 4];
            a2[3] = p2[(qr + 8) * 36 + c + 4];
            #pragma unroll
            for (int nc = 0; nc < 4; nc++) {
                uint32_t b[2];
                b[0] = sV[(kc * 8 + qc) * 40 + nc * 8 + qr];
                b[1] = sV[(kc * 8 + qc + 4) * 40 + nc * 8 + qr];
                mma_tf32(of[0][nc], a1, b);
                mma_tf32(of[1][nc], a2, b);
            }
        }
    }

    // ---- epilogue: quad-reduce l, write RAW partials (no normalization) ----
    #pragma unroll
    for (int s = 1; s < 4; s <<= 1) {
        #pragma unroll
        for (int hf = 0; hf < 2; hf++) {
            lacc[hf][0] += __shfl_xor_sync(0xffffffffu, lacc[hf][0], s);
            lacc[hf][1] += __shfl_xor_sync(0xffffffffu, lacc[hf][1], s);
        }
    }

    const int row_lo = i0 + warp * 16 + qr;
    // o partial base: (((spl*4 + h)*4096 + row)*2 + state)*32
    const int b_lo = ((spl * 4 + h) * 4096 + row_lo) * 2;
    const int b_hi = b_lo + 16;   // row_lo + 8 -> +8*2
    #pragma unroll
    for (int st = 0; st < 2; st++) {
        #pragma unroll
        for (int nc = 0; nc < 4; nc++) {
            const int col = nc * 8 + qc * 2;
            *(float2*)&g_po[(b_lo + st) * 32 + col] =
                make_float2(of[st][nc][0], of[st][nc][1]);
            *(float2*)&g_po[(b_hi + st) * 32 + col] =
                make_float2(of[st][nc][2], of[st][nc][3]);
        }
    }
    if (qc == 0) {
        #pragma unroll
        for (int st = 0; st < 2; st++) {
            g_pl[b_lo + st] = lacc[st][0];
            g_pl[b_hi + st] = lacc[st][1];
        }
    }
}

// ===========================================================================
// Kernel 3: split-K reduce + differential combine.
// out[h,n,d] = (sum_s o1)/(sum_s l1) - LAMBDA * (sum_s o2)/(sum_s l2)
// ===========================================================================
__global__ __launch_bounds__(256) void diff_reduce(float* __restrict__ out) {
    const int idx = blockIdx.x * 256 + threadIdx.x;   // over 4*4096*32
    const int d   = idx & 31;
    const int hn  = idx >> 5;                          // h*4096 + n

    const int STRIDE_O = 4 * 4096 * 2 * 32;
    const int STRIDE_L = 4 * 4096 * 2;
    const int bo = hn * 2 * 32;
    const int bl = hn * 2;

    float o1 = g_po[bo + d]                + g_po[STRIDE_O + bo + d];
    float o2 = g_po[bo + 32 + d]           + g_po[STRIDE_O + bo + 32 + d];
    float l1 = g_pl[bl]                    + g_pl[STRIDE_L + bl];
    float l2 = g_pl[bl + 1]                + g_pl[STRIDE_L + bl + 1];

    out[idx] = o1 / l1 - LAMBDA_F * (o2 / l2);
}

// ===========================================================================
extern "C" void kernel_launch(void* const* d_in, const int* in_sizes, int n_in,
                              void* d_out, int out_size) {
    const float* x = (const float*)d_in[0];       // (1,128,32,32,32)
    const float* w = (const float*)d_in[1];       // (384,128)
    float* out = (float*)d_out;                   // (1,128,16,16,16) fp32

    qkv_proj_kernel<<<dim3(64, 6), 256>>>(x, w);
    diff_attn_mma<<<dim3(64, 4, NSPLIT), 128>>>();
    diff_reduce<<<(4 * 4096 * 32) / 256, 256>>>(out);
}

// round 14
// speedup vs baseline: 8.5441x; 1.7377x over previous
#include <cuda_runtime.h>
#include <cstdint>
#include <math.h>

// Problem constants
//   x: (1,128,32,32,32) fp32 ; w_qkv: (384,128) fp32
//   subsample ::2 -> N = 4096 tokens, HEADS=4, head_dim=32, d_half=16
//   scale=1/sqrt(32), LAMBDA=0.1
//   out flat index = h*131072 + n*32 + d  (validated R4/R5)

#define N_TOK    4096
#define LAMBDA_F 0.1f
#define NSPLIT   2
#define KEYS_PER_SPLIT (N_TOK / NSPLIT)
#define TILES_PER_SPLIT (KEYS_PER_SPLIT / 32)
// scale * log2(e): scores computed directly in log2 domain for raw ex2
#define QSCALE_LOG2E 0.2550347222435f

// Scratch (device globals — no allocation)
__device__ float g_qkv[384 * 4096];        // q,k rows: [o][n], o = h*96 + r
__device__ float g_vT[4 * 4096 * 32];      // v: [h][n][d]
// split-K partials: o [split][h][row][state][d], l [split][h][row][state]
__device__ float g_po[NSPLIT * 4 * 4096 * 2 * 32];
__device__ float g_pl[NSPLIT * 4 * 4096 * 2];

// ---------------------------------------------------------------------------
__device__ __forceinline__ uint32_t f2tf32(float x) {
    uint32_t t;
    asm("cvt.rna.tf32.f32 %0, %1;" : "=r"(t) : "f"(x));
    return t;
}
__device__ __forceinline__ float ex2f(float x) {
    float y;
    asm("ex2.approx.ftz.f32 %0, %1;" : "=f"(y) : "f"(x));
    return y;
}
// pack {lo, hi} -> bf16x2 (cvt.rn.bf16x2.f32 d, hi, lo)
__device__ __forceinline__ uint32_t pack_bf16x2(float lo, float hi) {
    uint32_t r;
    asm("cvt.rn.bf16x2.f32 %0, %1, %2;" : "=r"(r) : "f"(hi), "f"(lo));
    return r;
}
// D += A * B  (m16n8k8, tf32 in, fp32 accum)
__device__ __forceinline__ void mma_tf32(float* d, const uint32_t* a, const uint32_t* b) {
    asm volatile(
        "mma.sync.aligned.m16n8k8.row.col.f32.tf32.tf32.f32 "
        "{%0,%1,%2,%3}, {%4,%5,%6,%7}, {%8,%9}, {%0,%1,%2,%3};"
        : "+f"(d[0]), "+f"(d[1]), "+f"(d[2]), "+f"(d[3])
        : "r"(a[0]), "r"(a[1]), "r"(a[2]), "r"(a[3]), "r"(b[0]), "r"(b[1]));
}
// D += A * B  (m16n8k16, bf16 in, fp32 accum)
__device__ __forceinline__ void mma_bf16(float* d, const uint32_t* a, const uint32_t* b) {
    asm volatile(
        "mma.sync.aligned.m16n8k16.row.col.f32.bf16.bf16.f32 "
        "{%0,%1,%2,%3}, {%4,%5,%6,%7}, {%8,%9}, {%0,%1,%2,%3};"
        : "+f"(d[0]), "+f"(d[1]), "+f"(d[2]), "+f"(d[3])
        : "r"(a[0]), "r"(a[1]), "r"(a[2]), "r"(a[3]), "r"(b[0]), "r"(b[1]));
}

// ===========================================================================
// Kernel 1: QKV projection with strided (::2) gather. (unchanged, proven)
// ===========================================================================
__global__ __launch_bounds__(256) void qkv_proj_kernel(const float* __restrict__ x,
                                                       const float* __restrict__ w) {
    __shared__ float sW[64 * 64];
    __shared__ float sX[64 * 64];
    const int tid = threadIdx.x;
    const int n0 = blockIdx.x * 64;
    const int o0 = blockIdx.y * 64;
    const int tx = tid & 15;
    const int ty = tid >> 4;

    float acc[4][4] = {};

    for (int k0 = 0; k0 < 128; k0 += 64) {
        __syncthreads();
        for (int i = tid; i < 64 * 16; i += 256) {
            int r = i >> 4, q4 = i & 15;
            *(float4*)&sW[r * 64 + q4 * 4] =
                *(const float4*)&w[(o0 + r) * 128 + k0 + q4 * 4];
        }
        for (int i = tid; i < 64 * 64; i += 256) {
            int cl = i >> 6, j = i & 63;
            int n = n0 + j;
            int hh = n >> 8, ww = (n >> 4) & 15, zz = n & 15;
            sX[cl * 64 + j] = x[(k0 + cl) * 32768 + hh * 2048 + ww * 64 + zz * 2];
        }
        __syncthreads();

        #pragma unroll
        for (int k = 0; k < 64; k += 4) {
            float xk[4][4];
            #pragma unroll
            for (int kk = 0; kk < 4; kk++) {
                float4 xv = *(float4*)&sX[(k + kk) * 64 + 4 * tx];
                xk[kk][0] = xv.x; xk[kk][1] = xv.y; xk[kk][2] = xv.z; xk[kk][3] = xv.w;
            }
            #pragma unroll
            for (int i = 0; i < 4; i++) {
                float4 wv = *(float4*)&sW[(4 * ty + i) * 64 + k];
                float wk[4] = {wv.x, wv.y, wv.z, wv.w};
                #pragma unroll
                for (int kk = 0; kk < 4; kk++)
                    #pragma unroll
                    for (int j = 0; j < 4; j++)
                        acc[i][j] += wk[kk] * xk[kk][j];
            }
        }
    }

    #pragma unroll
    for (int i = 0; i < 4; i++) {
        int o = o0 + 4 * ty + i;
        int r = o % 96;
        if (r < 64) {
            *(float4*)&g_qkv[o * 4096 + n0 + 4 * tx] =
                make_float4(acc[i][0], acc[i][1], acc[i][2], acc[i][3]);
        } else {
            int h = o / 96, d = r - 64;
            int nb = n0 + 4 * tx;
            #pragma unroll
            for (int j = 0; j < 4; j++)
                g_vT[(h * 4096 + nb + j) * 32 + d] = acc[i][j];
        }
    }
}

// ===========================================================================
// Kernel 2: dual-softmax attention, tf32 QK + register-resident P + bf16 PV.
// grid (64 row-tiles, 4 heads, 2 splits) = 512 CTAs, 128 threads (4 warps).
// S D-fragments exp'd in registers and packed as bf16 m16n8k16 A-fragments:
// P never touches shared memory.
// ===========================================================================
__global__ __launch_bounds__(128, 4) void diff_attn_mma(void) {
    __shared__ __align__(16) uint32_t sK [32 * 40];  // K fp32 bits [dim][key], pad 40
    __shared__ __align__(16) uint32_t sVb[16 * 40];  // V bf16x2 [keypair][dim], pad 40

    const int tid  = threadIdx.x;
    const int lane = tid & 31;
    const int warp = tid >> 5;
    const int h    = blockIdx.y;
    const int i0   = blockIdx.x * 64;
    const int spl  = blockIdx.z;
    const int kbase = spl * KEYS_PER_SPLIT;

    const float* qb = g_qkv + (h * 96) * 4096;
    const float* kb = qb + 32 * 4096;
    const float* vb = g_vT + h * 4096 * 32;

    const int qr = lane >> 2;   // 0..7
    const int qc = lane & 3;    // 0..3

    // ---- persistent Q fragments (rna->tf32, scale*log2e folded) ----
    uint32_t qf[2][2][4];
    {
        const int r = i0 + warp * 16 + qr;
        #pragma unroll
        for (int hf = 0; hf < 2; hf++)
            #pragma unroll
            for (int kc = 0; kc < 2; kc++) {
                int d = hf * 16 + kc * 8 + qc;
                qf[hf][kc][0] = f2tf32(qb[d * 4096 + r] * QSCALE_LOG2E);
                qf[hf][kc][1] = f2tf32(qb[d * 4096 + r + 8] * QSCALE_LOG2E);
                qf[hf][kc][2] = f2tf32(qb[(d + 4) * 4096 + r] * QSCALE_LOG2E);
                qf[hf][kc][3] = f2tf32(qb[(d + 4) * 4096 + r + 8] * QSCALE_LOG2E);
            }
    }

    float of[2][4][4] = {};    // [state][nc(dim 8-chunk)][frag]
    float lacc[2][2] = {};     // [state][lo/hi row]

    // fill mapping: 128 threads; K: rows pd,pd+16 x 4 keys; V: keypair kp x 4 dims
    const int pd = tid >> 3;          // 0..15
    const int pc = (tid & 7) * 4;     // 0..28

    float4 kfA, kfB, vfA, vfB;
    kfA = *(const float4*)&kb[pd * 4096 + kbase + pc];
    kfB = *(const float4*)&kb[(pd + 16) * 4096 + kbase + pc];
    vfA = *(const float4*)&vb[(kbase + 2 * pd) * 32 + pc];
    vfB = *(const float4*)&vb[(kbase + 2 * pd + 1) * 32 + pc];

    for (int jt = 0; jt < TILES_PER_SPLIT; jt++) {
        __syncthreads();   // previous tile's smem fully consumed
        *(float4*)&sK[pd * 40 + pc]        = *(float4*)&kfA;
        *(float4*)&sK[(pd + 16) * 40 + pc] = *(float4*)&kfB;
        {   // pack V pairs (even key -> low half) into bf16x2
            uint4 vp;
            vp.x = pack_bf16x2(vfA.x, vfB.x);
            vp.y = pack_bf16x2(vfA.y, vfB.y);
            vp.z = pack_bf16x2(vfA.z, vfB.z);
            vp.w = pack_bf16x2(vfA.w, vfB.w);
            *(uint4*)&sVb[pd * 40 + pc] = vp;
        }
        __syncthreads();

        if (jt < TILES_PER_SPLIT - 1) {   // register prefetch of next tile
            const int j0 = kbase + (jt + 1) * 32;
            kfA = *(const float4*)&kb[pd * 4096 + j0 + pc];
            kfB = *(const float4*)&kb[(pd + 16) * 4096 + j0 + pc];
            vfA = *(const float4*)&vb[(j0 + 2 * pd) * 32 + pc];
            vfB = *(const float4*)&vb[(j0 + 2 * pd + 1) * 32 + pc];
        }

        // ---- MMA1 (tf32) + exp + in-register bf16 A-frag pack, both states ----
        uint32_t pa[2][2][4];   // [state][k16-chunk][a-frag]
        #pragma unroll
        for (int hf = 0; hf < 2; hf++) {
            float sf[4][4] = {};
            #pragma unroll
            for (int kc = 0; kc < 2; kc++) {
                const int drow = hf * 16 + kc * 8 + qc;
                #pragma unroll
                for (int nc = 0; nc < 4; nc++) {
                    uint32_t b[2];
                    b[0] = sK[drow * 40 + nc * 8 + qr];
                    b[1] = sK[(drow + 4) * 40 + nc * 8 + qr];
                    mma_tf32(sf[nc], qf[hf][kc], b);
                }
            }
            float ll = 0.f, lh = 0.f;
            #pragma unroll
            for (int nc = 0; nc < 4; nc++) {
                float e0 = ex2f(sf[nc][0]);
                float e1 = ex2f(sf[nc][1]);
                float e2 = ex2f(sf[nc][2]);
                float e3 = ex2f(sf[nc][3]);
                ll += e0 + e1;
                lh += e2 + e3;
                // chunk = nc>>1 (keys 0..15 from nc 0,1 ; keys 16..31 from nc 2,3)
                const int ch = nc >> 1;
                const int aoff = (nc & 1) * 2;   // nc even -> a0,a1 ; odd -> a2,a3
                pa[hf][ch][aoff + 0] = pack_bf16x2(e0, e1);
                pa[hf][ch][aoff + 1] = pack_bf16x2(e2, e3);
            }
            lacc[hf][0] += ll;
            lacc[hf][1] += lh;
        }

        // ---- PV (bf16 m16n8k16): O_s += P_s x V, V fragments shared ----
        #pragma unroll
        for (int c = 0; c < 2; c++) {
            #pragma unroll
            for (int nc = 0; nc < 4; nc++) {
                uint32_t b[2];
                b[0] = sVb[(c * 8 + qc) * 40 + nc * 8 + qr];
                b[1] = sVb[(c * 8 + qc + 4) * 40 + nc * 8 + qr];
                mma_bf16(of[0][nc], pa[0][c], b);
                mma_bf16(of[1][nc], pa[1][c], b);
            }
        }
    }

    // ---- epilogue: quad-reduce l, write RAW partials (no normalization) ----
    #pragma unroll
    for (int s = 1; s < 4; s <<= 1) {
        #pragma unroll
        for (int hf = 0; hf < 2; hf++) {
            lacc[hf][0] += __shfl_xor_sync(0xffffffffu, lacc[hf][0], s);
            lacc[hf][1] += __shfl_xor_sync(0xffffffffu, lacc[hf][1], s);
        }
    }

    const int row_lo = i0 + warp * 16 + qr;
    const int b_lo = ((spl * 4 + h) * 4096 + row_lo) * 2;
    const int b_hi = b_lo + 16;   // row_lo + 8
    #pragma unroll
    for (int st = 0; st < 2; st++) {
        #pragma unroll
        for (int nc = 0; nc < 4; nc++) {
            const int col = nc * 8 + qc * 2;
            *(float2*)&g_po[(b_lo + st) * 32 + col] =
                make_float2(of[st][nc][0], of[st][nc][1]);
            *(float2*)&g_po[(b_hi + st) * 32 + col] =
                make_float2(of[st][nc][2], of[st][nc][3]);
        }
    }
    if (qc == 0) {
        #pragma unroll
        for (int st = 0; st < 2; st++) {
            g_pl[b_lo + st] = lacc[st][0];
            g_pl[b_hi + st] = lacc[st][1];
        }
    }
}

// ===========================================================================
// Kernel 3: split-K reduce + differential combine.
// out[h,n,d] = (sum_s o1)/(sum_s l1) - LAMBDA * (sum_s o2)/(sum_s l2)
// ===========================================================================
__global__ __launch_bounds__(256) void diff_reduce(float* __restrict__ out) {
    const int idx = blockIdx.x * 256 + threadIdx.x;   // over 4*4096*32
    const int d   = idx & 31;
    const int hn  = idx >> 5;                          // h*4096 + n

    const int STRIDE_O = 4 * 4096 * 2 * 32;
    const int STRIDE_L = 4 * 4096 * 2;
    const int bo = hn * 2 * 32;
    const int bl = hn * 2;

    float o1 = g_po[bo + d]      + g_po[STRIDE_O + bo + d];
    float o2 = g_po[bo + 32 + d] + g_po[STRIDE_O + bo + 32 + d];
    float l1 = g_pl[bl]          + g_pl[STRIDE_L + bl];
    float l2 = g_pl[bl + 1]      + g_pl[STRIDE_L + bl + 1];

    out[idx] = o1 / l1 - LAMBDA_F * (o2 / l2);
}

// ===========================================================================
extern "C" void kernel_launch(void* const* d_in, const int* in_sizes, int n_in,
                              void* d_out, int out_size) {
    const float* x = (const float*)d_in[0];       // (1,128,32,32,32)
    const float* w = (const float*)d_in[1];       // (384,128)
    float* out = (float*)d_out;                   // (1,128,16,16,16) fp32

    qkv_proj_kernel<<<dim3(64, 6), 256>>>(x, w);
    diff_attn_mma<<<dim3(64, 4, NSPLIT), 128>>>();
    diff_reduce<<<(4 * 4096 * 32) / 256, 256>>>(out);
}